// round 10
// baseline (speedup 1.0000x reference)
#include <cuda_runtime.h>
#include <cstdint>

#define NTOK  4096
#define CDIM  256
#define HIDD  64
#define BATCH 4

// Projection scratch (tf32-rounded): q,k: [src][b][n][64]; v TRANSPOSED: [src][b][c][m]
__device__ float g_q[2][BATCH][NTOK][HIDD];
__device__ float g_k[2][BATCH][NTOK][HIDD];
__device__ float g_vt[2][BATCH][CDIM][NTOK];

// ---------------------------------------------------------------------------
// helpers
// ---------------------------------------------------------------------------
__device__ __forceinline__ float to_tf32(float x) {
    uint32_t u;
    asm("cvt.rna.tf32.f32 %0, %1;" : "=r"(u) : "f"(x));
    return __uint_as_float(u);
}

__device__ __forceinline__ void mma_tf32(float c[4],
                                         uint32_t a0, uint32_t a1, uint32_t a2, uint32_t a3,
                                         uint32_t b0, uint32_t b1) {
    asm volatile(
        "mma.sync.aligned.m16n8k8.row.col.f32.tf32.tf32.f32 "
        "{%0,%1,%2,%3}, {%4,%5,%6,%7}, {%8,%9}, {%0,%1,%2,%3};\n"
        : "+f"(c[0]), "+f"(c[1]), "+f"(c[2]), "+f"(c[3])
        : "r"(a0), "r"(a1), "r"(a2), "r"(a3), "r"(b0), "r"(b1));
}

// fast exp on the FMA pipe
__device__ __forceinline__ float fexp(float x) {
    float t = x * 1.4426950408889634f;
    t = fmaxf(t, -126.0f);
    float fi = t + 12582912.0f;
    int   ii = __float_as_int(fi) - 0x4B400000;
    float fr = t - (fi - 12582912.0f);
    float u  = fr * 0.6931471805599453f;
    float p  = 8.3333337e-3f;
    p = fmaf(p, u, 4.1666668e-2f);
    p = fmaf(p, u, 0.16666667f);
    p = fmaf(p, u, 0.5f);
    p = fmaf(p, u, 1.0f);
    p = fmaf(p, u, 1.0f);
    return __int_as_float(__float_as_int(p) + (ii << 23));
}

// ---------------------------------------------------------------------------
// Projection via tf32 mma (unchanged from R9, passing)
// ---------------------------------------------------------------------------
__global__ __launch_bounds__(256) void proj_kernel(
    const float* __restrict__ x1, const float* __restrict__ x2,
    const float* __restrict__ Wq, const float* __restrict__ bq,
    const float* __restrict__ Wk, const float* __restrict__ bk,
    const float* __restrict__ Wv, const float* __restrict__ bv)
{
    int ntile = blockIdx.x;
    int otile = blockIdx.y;
    int src   = blockIdx.z >> 2;
    int b     = blockIdx.z & 3;
    const float* x = src ? x2 : x1;

    const float* W; const float* bias; int oofs;
    if (otile == 0)      { W = Wq; bias = bq; oofs = 0; }
    else if (otile == 1) { W = Wk; bias = bk; oofs = 0; }
    else                 { W = Wv; bias = bv; oofs = (otile - 2) * 64; }

    __shared__ float Ws[64][68];
    __shared__ float Xs[64][72];

    int t    = threadIdx.x;
    int warp = t >> 5, lane = t & 31;
    int g    = lane >> 2, tig = lane & 3;
    int wr   = warp >> 1, wc = warp & 1;
    int n0   = ntile * 64;

    float acc[4][4] = {};
    const float4* W4 = (const float4*)W;

    for (int cc = 0; cc < CDIM; cc += 64) {
        for (int i = t; i < 1024; i += 256) {
            int r = i >> 4, kq = i & 15;
            float4 w = W4[(size_t)(oofs + r) * 64 + (cc >> 2) + kq];
            Ws[r][kq * 4 + 0] = to_tf32(w.x);
            Ws[r][kq * 4 + 1] = to_tf32(w.y);
            Ws[r][kq * 4 + 2] = to_tf32(w.z);
            Ws[r][kq * 4 + 3] = to_tf32(w.w);
        }
        const float4* X4 = (const float4*)x;
        for (int i = t; i < 1024; i += 256) {
            int r = i >> 4, cq = i & 15;
            float4 v = X4[(size_t)(b * CDIM + cc + r) * (NTOK / 4) + (n0 >> 2) + cq];
            Xs[r][cq * 4 + 0] = to_tf32(v.x);
            Xs[r][cq * 4 + 1] = to_tf32(v.y);
            Xs[r][cq * 4 + 2] = to_tf32(v.z);
            Xs[r][cq * 4 + 3] = to_tf32(v.w);
        }
        __syncthreads();
        int ob = wr * 16;
        #pragma unroll
        for (int kk = 0; kk < 8; kk++) {
            int k0 = kk * 8;
            uint32_t a0 = __float_as_uint(Ws[ob + g][k0 + tig]);
            uint32_t a1 = __float_as_uint(Ws[ob + g + 8][k0 + tig]);
            uint32_t a2 = __float_as_uint(Ws[ob + g][k0 + tig + 4]);
            uint32_t a3 = __float_as_uint(Ws[ob + g + 8][k0 + tig + 4]);
            #pragma unroll
            for (int j = 0; j < 4; j++) {
                int nb = wc * 32 + j * 8;
                uint32_t b0 = __float_as_uint(Xs[k0 + tig][nb + g]);
                uint32_t b1 = __float_as_uint(Xs[k0 + tig + 4][nb + g]);
                mma_tf32(acc[j], a0, a1, a2, a3, b0, b1);
            }
        }
        __syncthreads();
    }

    float* stage = &Ws[0][0];
    int o0 = wr * 16 + g, o1 = o0 + 8;
    float bz0 = bias[oofs + o0], bz1 = bias[oofs + o1];

    if (otile < 2) {
        #pragma unroll
        for (int j = 0; j < 4; j++) {
            int nl = wc * 32 + j * 8 + tig * 2;
            stage[(nl)     * 64 + o0] = to_tf32(acc[j][0] + bz0);
            stage[(nl + 1) * 64 + o0] = to_tf32(acc[j][1] + bz0);
            stage[(nl)     * 64 + o1] = to_tf32(acc[j][2] + bz1);
            stage[(nl + 1) * 64 + o1] = to_tf32(acc[j][3] + bz1);
        }
        __syncthreads();
        float* outb = (otile == 0) ? &g_q[src][b][0][0] : &g_k[src][b][0][0];
        for (int i = t; i < 4096; i += 256) {
            int nl = i >> 6, o = i & 63;
            outb[(size_t)(n0 + nl) * 64 + o] = stage[nl * 64 + o];
        }
    } else {
        #pragma unroll
        for (int j = 0; j < 4; j++) {
            int nl = wc * 32 + j * 8 + tig * 2;
            stage[o0 * 64 + nl]     = to_tf32(acc[j][0] + bz0);
            stage[o0 * 64 + nl + 1] = to_tf32(acc[j][1] + bz0);
            stage[o1 * 64 + nl]     = to_tf32(acc[j][2] + bz1);
            stage[o1 * 64 + nl + 1] = to_tf32(acc[j][3] + bz1);
        }
        __syncthreads();
        float* outb = &g_vt[src][b][oofs][0];
        for (int i = t; i < 4096; i += 256) {
            int o = i >> 6, nl = i & 63;
            outb[(size_t)o * NTOK + n0 + nl] = stage[o * 64 + nl];
        }
    }
}

// ---------------------------------------------------------------------------
// Flash cross-attention, tf32 mma, O^T = V^T P^T.
// grid (N/64, B, 2), block 256, 2 CTAs/SM.
// Q fragments live in registers; K double-buffered (X0/X1, each also reused
// as the P buffer for its iteration). Per iter:
//   S=QK^T (no load wait) -> copy K_{i+1}+V_i -> sync -> softmax/P -> sync
//   -> O^T += V^T P^T (kk-outer, shared B fragments) -> sync.
// ---------------------------------------------------------------------------
#define PADH 68
#define XSTRIDE (64 * PADH)
#define SM_VT   0                        // 256 x 68 (V^T tile; Q staging; O^T staging)
#define SM_X0   (256 * PADH)             // 64 x 68  (K/P buffer 0)
#define SM_X1   (SM_X0 + XSTRIDE)        // 64 x 68  (K/P buffer 1)
#define SM_RS   (SM_X1 + XSTRIDE)        // 128
#define SM_INV  (SM_RS + 128)            // 64
#define ATTN_SMEM_FLOATS (SM_INV + 64)   // 26304 floats = 105216 B

__global__ __launch_bounds__(256, 2) void attn_kernel(
    const float* __restrict__ x1, const float* __restrict__ x2,
    const float* __restrict__ gamma_p, float* __restrict__ out)
{
    int qtile = blockIdx.x, b = blockIdx.y, dir = blockIdx.z;
    int srckv = dir ^ 1;
    const float* xq = dir ? x2 : x1;
    int n0 = qtile * 64;

    extern __shared__ float sm[];
    float* Vt  = sm + SM_VT;
    float* rs  = sm + SM_RS;
    float* inv = sm + SM_INV;

    int t    = threadIdx.x;
    int warp = t >> 5, lane = t & 31;
    int g    = lane >> 2, tig = lane & 3;
    int wr   = warp >> 1, wc = warp & 1;
    int qb   = wr * 16;        // S-phase q-row base
    int cb   = warp * 32;      // PV-phase c-row base

    const float4* kg4  = (const float4*)&g_k[srckv][b][0][0];
    const float4* vtg4 = (const float4*)&g_vt[srckv][b][0][0];

    // ---- prologue: stage Q in Vt area, lift fragments to registers ----
    {
        const float4* qg4 = (const float4*)&g_q[dir][b][n0][0];
        #pragma unroll
        for (int j = 0; j < 4; j++) {
            int i = t + 256 * j;
            int r = i >> 4, cq = i & 15;
            *(float4*)&Vt[r * PADH + cq * 4] = qg4[i];
        }
    }
    if (t < 128) rs[t] = 0.f;
    __syncthreads();

    float qf[8][4];
    #pragma unroll
    for (int kk = 0; kk < 8; kk++) {
        int k0 = kk * 8;
        qf[kk][0] = Vt[(qb + g)     * PADH + k0 + tig];
        qf[kk][1] = Vt[(qb + g + 8) * PADH + k0 + tig];
        qf[kk][2] = Vt[(qb + g)     * PADH + k0 + tig + 4];
        qf[kk][3] = Vt[(qb + g + 8) * PADH + k0 + tig + 4];
    }
    // K_0 into X0
    {
        float* X0 = sm + SM_X0;
        #pragma unroll
        for (int j = 0; j < 4; j++) {
            int i = t + 256 * j;
            int r = i >> 4, cq = i & 15;
            *(float4*)&X0[r * PADH + cq * 4] = kg4[i];
        }
    }
    float oacc[16][4] = {};
    __syncthreads();

    for (int it = 0; it < NTOK / 64; it++) {
        float* Xk = sm + SM_X0 + (it & 1) * XSTRIDE;         // K_it, later P_it
        float* Xn = sm + SM_X0 + ((it + 1) & 1) * XSTRIDE;   // K_{it+1} dest

        // ---- S = Q K^T (K already resident; Q in regs) ----
        float sf[4][4] = {};
        #pragma unroll
        for (int kk = 0; kk < 8; kk++) {
            int k0 = kk * 8;
            uint32_t a0 = __float_as_uint(qf[kk][0]);
            uint32_t a1 = __float_as_uint(qf[kk][1]);
            uint32_t a2 = __float_as_uint(qf[kk][2]);
            uint32_t a3 = __float_as_uint(qf[kk][3]);
            #pragma unroll
            for (int nb = 0; nb < 4; nb++) {
                int m = wc * 32 + nb * 8;
                uint32_t b0 = __float_as_uint(Xk[(m + g) * PADH + k0 + tig]);
                uint32_t b1 = __float_as_uint(Xk[(m + g) * PADH + k0 + tig + 4]);
                mma_tf32(sf[nb], a0, a1, a2, a3, b0, b1);
            }
        }

        // ---- copy K_{it+1} -> Xn and V_it -> Vt (off critical path) ----
        {
            int itn = (it < NTOK / 64 - 1) ? it + 1 : it;
            const float4* ksrc = kg4 + (size_t)itn * 1024;
            #pragma unroll
            for (int j = 0; j < 4; j++) {
                int i = t + 256 * j;
                int r = i >> 4, cq = i & 15;
                *(float4*)&Xn[r * PADH + cq * 4] = ksrc[i];
            }
            #pragma unroll
            for (int j = 0; j < 16; j++) {
                int i = t + 256 * j;
                int c = i >> 4, mq = i & 15;
                *(float4*)&Vt[c * PADH + mq * 4] =
                    vtg4[(size_t)c * (NTOK / 4) + it * 16 + mq];
            }
        }
        __syncthreads();   // #1: S reads of Xk done; K/V stores done

        // ---- no-max softmax; P -> Xk ----
        {
            float ps0 = 0.f, ps1 = 0.f;
            #pragma unroll
            for (int nb = 0; nb < 4; nb++) {
                float p0 = fexp(sf[nb][0]);
                float p1 = fexp(sf[nb][1]);
                float p2 = fexp(sf[nb][2]);
                float p3 = fexp(sf[nb][3]);
                ps0 += p0 + p1;
                ps1 += p2 + p3;
                int col = wc * 32 + nb * 8 + tig * 2;
                Xk[(qb + g)     * PADH + col]     = to_tf32(p0);
                Xk[(qb + g)     * PADH + col + 1] = to_tf32(p1);
                Xk[(qb + g + 8) * PADH + col]     = to_tf32(p2);
                Xk[(qb + g + 8) * PADH + col + 1] = to_tf32(p3);
            }
            ps0 += __shfl_xor_sync(0xffffffffu, ps0, 1);
            ps0 += __shfl_xor_sync(0xffffffffu, ps0, 2);
            ps1 += __shfl_xor_sync(0xffffffffu, ps1, 1);
            ps1 += __shfl_xor_sync(0xffffffffu, ps1, 2);
            if (tig == 0) {
                rs[wc * 64 + qb + g]     += ps0;
                rs[wc * 64 + qb + g + 8] += ps1;
            }
        }
        __syncthreads();   // #2: P + V visible

        // ---- O^T += V^T P^T, kk-outer (B fragments shared by both c-subtiles) ----
        #pragma unroll
        for (int kk = 0; kk < 8; kk++) {
            int k0 = kk * 8;
            uint32_t A0[4], A1[4];
            A0[0] = __float_as_uint(Vt[(cb + g)      * PADH + k0 + tig]);
            A0[1] = __float_as_uint(Vt[(cb + g + 8)  * PADH + k0 + tig]);
            A0[2] = __float_as_uint(Vt[(cb + g)      * PADH + k0 + tig + 4]);
            A0[3] = __float_as_uint(Vt[(cb + g + 8)  * PADH + k0 + tig + 4]);
            A1[0] = __float_as_uint(Vt[(cb + g + 16) * PADH + k0 + tig]);
            A1[1] = __float_as_uint(Vt[(cb + g + 24) * PADH + k0 + tig]);
            A1[2] = __float_as_uint(Vt[(cb + g + 16) * PADH + k0 + tig + 4]);
            A1[3] = __float_as_uint(Vt[(cb + g + 24) * PADH + k0 + tig + 4]);
            #pragma unroll
            for (int nb = 0; nb < 8; nb++) {
                int q = nb * 8;
                uint32_t b0 = __float_as_uint(Xk[(q + g) * PADH + k0 + tig]);
                uint32_t b1 = __float_as_uint(Xk[(q + g) * PADH + k0 + tig + 4]);
                mma_tf32(oacc[nb],     A0[0], A0[1], A0[2], A0[3], b0, b1);
                mma_tf32(oacc[8 + nb], A1[0], A1[1], A1[2], A1[3], b0, b1);
            }
        }
        __syncthreads();   // #3: PV reads done; buffers free for next iter
    }

    // ---- epilogue ----
    if (t < 64) inv[t] = 1.f / (rs[t] + rs[64 + t]);

    float* stage = Vt;   // [c][q] stride 65
    #pragma unroll
    for (int mt2 = 0; mt2 < 2; mt2++) {
        int crow = cb + mt2 * 16;
        #pragma unroll
        for (int nb = 0; nb < 8; nb++) {
            int q = nb * 8 + tig * 2;
            stage[(crow + g)     * 65 + q]     = oacc[mt2 * 8 + nb][0];
            stage[(crow + g)     * 65 + q + 1] = oacc[mt2 * 8 + nb][1];
            stage[(crow + g + 8) * 65 + q]     = oacc[mt2 * 8 + nb][2];
            stage[(crow + g + 8) * 65 + q + 1] = oacc[mt2 * 8 + nb][3];
        }
    }
    __syncthreads();

    float gm = gamma_p[0];
    size_t obase = ((size_t)(dir * BATCH + b)) * CDIM * NTOK;
    const float* xb = xq + (size_t)b * CDIM * NTOK;
    for (int i = t; i < 64 * 256; i += 256) {
        int c = i >> 6, nl = i & 63;
        size_t idx = (size_t)c * NTOK + n0 + nl;
        out[obase + idx] = xb[idx] + gm * inv[nl] * stage[c * 65 + nl];
    }
}

extern "C" void kernel_launch(void* const* d_in, const int* in_sizes, int n_in,
                              void* d_out, int out_size)
{
    const float* x1    = (const float*)d_in[0];
    const float* x2    = (const float*)d_in[1];
    const float* Wq    = (const float*)d_in[2];
    const float* bq    = (const float*)d_in[3];
    const float* Wk    = (const float*)d_in[4];
    const float* bk    = (const float*)d_in[5];
    const float* Wv    = (const float*)d_in[6];
    const float* bv    = (const float*)d_in[7];
    const float* gamma = (const float*)d_in[8];
    float* out = (float*)d_out;
    (void)in_sizes; (void)n_in; (void)out_size;

    size_t attn_smem = (size_t)ATTN_SMEM_FLOATS * sizeof(float);
    cudaFuncSetAttribute(attn_kernel, cudaFuncAttributeMaxDynamicSharedMemorySize,
                         (int)attn_smem);

    proj_kernel<<<dim3(NTOK / 64, 6, 2 * BATCH), 256>>>(x1, x2, Wq, bq, Wk, bk, Wv, bv);
    attn_kernel<<<dim3(NTOK / 64, BATCH, 2), 256, attn_smem>>>(x1, x2, gamma, out);
}